// round 7
// baseline (speedup 1.0000x reference)
#include <cuda_runtime.h>
#include <math.h>

#define BDIM   128
#define TENC   64
#define TDEC   32
#define DIN    2048
#define DW     300
#define HID    512
#define G4     2048   // 4*HID

// ---------------- scratch (device globals: no allocation allowed) -------------
// NOTE: these symbols are ONLY referenced from device code. Passing them as
// kernel arguments from host code silently yields the HOST shadow address
// (valid over ATS on GB300 -> silent wrong-memory writes). Never do that.
__device__ float g_pre_enc[BDIM * TENC * G4];   // [b*TENC + t][4H]  64 MB
__device__ float g_pre_dec[BDIM * TDEC * G4];   // [b*TDEC + t][4H]  32 MB
__device__ float g_h[2][BDIM * HID];            // ping-pong hidden state
__device__ float g_c[BDIM * HID];               // cell state (in-place)
__device__ float g_dechs[TDEC * BDIM * HID];    // decoder h outputs [t][b][h]

__device__ __forceinline__ float sigm(float x) { return 1.0f / (1.0f + expf(-x)); }

// ---------------- init: zero h0 / c0 each replay ------------------------------
__global__ void init_state_kernel() {
    int i = blockIdx.x * blockDim.x + threadIdx.x;
    if (i < BDIM * HID) {
        g_h[0][i] = 0.0f;
        g_c[i] = 0.0f;
    }
}

// ---------------- plain-scalar tiled GEMM:  C = A @ W + bias ------------------
// 128x128 tile, BK=8, 256 threads, 8x8 micro-tile per thread (strided by 16).
// MODE 0: A = frames [8192 x 2048]      -> writes g_pre_enc (symbol)
// MODE 1: A-row = emb[ids[m]] (K=300)   -> writes g_pre_dec (symbol)
// MODE 2: A = g_dechs (symbol) [4096 x 512], N=300 -> writes Cout (d_out),
//         row m=(t*128+b) stored at Cout[(b*TDEC + t)*300 + n]
template <int MODE>
__global__ __launch_bounds__(256, 2)
void gemm_kernel(const float* __restrict__ A, const float* __restrict__ W,
                 const float* __restrict__ bias, float* __restrict__ Cout,
                 const int* __restrict__ ids, int M, int N, int K)
{
    __shared__ float As[8][128];   // [k][m]
    __shared__ float Bs[8][128];   // [k][n]

    // resolve destination INSIDE device code (symbols have device addresses here)
    float* C;
    if (MODE == 0)      C = g_pre_enc;
    else if (MODE == 1) C = g_pre_dec;
    else                C = Cout;

    const int bn0 = blockIdx.x * 128;
    const int bm0 = blockIdx.y * 128;
    const int tid = threadIdx.x;

    const int arow = tid >> 1;          // 0..127
    const int ak   = (tid & 1) * 4;     // 0 or 4
    const int bk   = tid >> 5;          // 0..7
    const int bn   = (tid & 31) * 4;    // 0..124

    const float* arow_ptr;
    if (MODE == 1) {
        arow_ptr = A + (long)ids[bm0 + arow] * K;     // embedding gather
    } else if (MODE == 2) {
        arow_ptr = g_dechs + (long)(bm0 + arow) * K;  // device symbol, device code
    } else {
        arow_ptr = A + (long)(bm0 + arow) * K;
    }

    const int tc = tid & 15;            // column group 0..15
    const int tr = tid >> 4;            // row group    0..15

    float acc[8][8];
    #pragma unroll
    for (int i = 0; i < 8; i++)
        #pragma unroll
        for (int j = 0; j < 8; j++) acc[i][j] = 0.0f;

    for (int kt = 0; kt < K; kt += 8) {
        #pragma unroll
        for (int s = 0; s < 4; s++) {
            int k = kt + ak + s;
            As[ak + s][arow] = (k < K) ? arow_ptr[k] : 0.0f;
        }
        #pragma unroll
        for (int s = 0; s < 4; s++) {
            int k = kt + bk;
            int col = bn0 + bn + s;
            Bs[bk][bn + s] = (k < K && col < N) ? W[(long)k * N + col] : 0.0f;
        }
        __syncthreads();

        #pragma unroll
        for (int k = 0; k < 8; k++) {
            float a[8], b[8];
            #pragma unroll
            for (int i = 0; i < 8; i++) a[i] = As[k][tr + i * 16];
            #pragma unroll
            for (int j = 0; j < 8; j++) b[j] = Bs[k][tc + j * 16];
            #pragma unroll
            for (int i = 0; i < 8; i++)
                #pragma unroll
                for (int j = 0; j < 8; j++)
                    acc[i][j] += a[i] * b[j];
        }
        __syncthreads();
    }

    #pragma unroll
    for (int i = 0; i < 8; i++) {
        int m = bm0 + tr + i * 16;
        #pragma unroll
        for (int j = 0; j < 8; j++) {
            int n = bn0 + tc + j * 16;
            if (n < N) {
                float v = acc[i][j] + bias[n];
                if (MODE == 2) {
                    int b = m & 127, t = m >> 7;    // m = t*128 + b
                    C[((long)b * TDEC + t) * (long)N + n] = v;
                } else {
                    C[(long)m * N + n] = v;
                }
            }
        }
    }
}

// ---------------- fused recurrent LSTM step -----------------------------------
// gates[b][g*512+j] = pre[b][t][g*512+j] + sum_k h[b][k]*Wh[k][g*512+j]
// Block tile: 32 b x 16 j x all 4 gates; 256 threads; grid (4, 32).
__global__ __launch_bounds__(256, 4)
void lstm_step_kernel(int phase /*0=enc,1=dec*/, int t, int s,
                      const float* __restrict__ Wh)
{
    __shared__ float hs[16][33];   // [k_local][b_local], padded
    __shared__ float Ws[16][64];   // [k_local][g*16 + jj]

    const float* pre = phase ? g_pre_dec : g_pre_enc;
    const int Tdim = phase ? TDEC : TENC;
    const float* hin = g_h[s & 1];
    float* hout = g_h[(s + 1) & 1];
    float* dechs = phase ? (g_dechs + (long)t * BDIM * HID) : (float*)0;

    const int tid = threadIdx.x;
    const int b0 = blockIdx.x * 32;
    const int j0 = blockIdx.y * 16;

    const int hb = tid >> 3;           // 0..31
    const int hk = (tid & 7) * 2;      // 0,2,...,14
    const int wk = tid >> 4;           // 0..15
    const int wq = tid & 15;
    const int wg = wq >> 2;            // gate 0..3
    const int wj = (wq & 3) * 4;       // 0,4,8,12

    const int jj = tid & 15;
    const int bq = tid >> 4;           // 0..15

    float acc[2][4] = {{0.f, 0.f, 0.f, 0.f}, {0.f, 0.f, 0.f, 0.f}};

    for (int k0 = 0; k0 < HID; k0 += 16) {
        hs[hk][hb]     = hin[(long)(b0 + hb) * HID + k0 + hk];
        hs[hk + 1][hb] = hin[(long)(b0 + hb) * HID + k0 + hk + 1];
        #pragma unroll
        for (int s4 = 0; s4 < 4; s4++) {
            Ws[wk][wg * 16 + wj + s4] =
                Wh[(long)(k0 + wk) * G4 + wg * HID + j0 + wj + s4];
        }
        __syncthreads();

        #pragma unroll
        for (int k = 0; k < 16; k++) {
            float h0 = hs[k][bq];
            float h1 = hs[k][bq + 16];
            #pragma unroll
            for (int g = 0; g < 4; g++) {
                float w = Ws[k][g * 16 + jj];
                acc[0][g] += h0 * w;
                acc[1][g] += h1 * w;
            }
        }
        __syncthreads();
    }

    #pragma unroll
    for (int bl = 0; bl < 2; bl++) {
        int b = b0 + bq + bl * 16;
        int j = j0 + jj;
        const float* pr = pre + ((long)b * Tdim + t) * G4 + j;
        float gi = acc[bl][0] + pr[0];
        float gj = acc[bl][1] + pr[512];
        float gf = acc[bl][2] + pr[1024];
        float go = acc[bl][3] + pr[1536];
        int idx = b * HID + j;
        float cn = g_c[idx] * sigm(gf + 1.0f) + sigm(gi) * tanhf(gj);
        g_c[idx] = cn;
        float hn = tanhf(cn) * sigm(go);
        hout[idx] = hn;
        if (dechs) dechs[idx] = hn;
    }
}

// ---------------- launch ------------------------------------------------------
// Inputs resolved BY ELEMENT COUNT (robust to metadata order), with positional
// fallback. Only harness-provided device pointers are passed to kernels.
extern "C" void kernel_launch(void* const* d_in, const int* in_sizes, int n_in,
                              void* d_out, int out_size) {
    (void)out_size;
    const float* frames  = 0;   // 16777216
    const int*   cap_ids = 0;   // 4096
    const float* emb     = 0;   // 9600000
    const float* W_enc   = 0;   // 5242880
    const float* b_enc   = 0;   // 2048 (first seen)
    const float* W_dec   = 0;   // 1662976
    const float* b_dec   = 0;   // 2048 (second seen)
    const float* W_out   = 0;   // 153600
    const float* b_out   = 0;   // 300

    for (int i = 0; i < n_in; i++) {
        long sz = in_sizes[i];
        const void* p = d_in[i];
        if      (sz == 16777216) frames  = (const float*)p;
        else if (sz == 4096)     cap_ids = (const int*)p;
        else if (sz == 9600000)  emb     = (const float*)p;
        else if (sz == 5242880)  W_enc   = (const float*)p;
        else if (sz == 1662976)  W_dec   = (const float*)p;
        else if (sz == 153600)   W_out   = (const float*)p;
        else if (sz == 300)      b_out   = (const float*)p;
        else if (sz == 2048) {
            if (!b_enc) b_enc = (const float*)p;
            else        b_dec = (const float*)p;
        }
    }
    if (!frames || !cap_ids || !emb || !W_enc || !b_enc || !W_dec || !b_dec ||
        !W_out || !b_out) {
        frames  = (const float*)d_in[0];
        cap_ids = (const int*)  d_in[1];
        emb     = (const float*)d_in[2];
        W_enc   = (const float*)d_in[3];
        b_enc   = (const float*)d_in[4];
        W_dec   = (const float*)d_in[5];
        b_dec   = (const float*)d_in[6];
        W_out   = (const float*)d_in[7];
        b_out   = (const float*)d_in[8];
    }
    float* out = (float*)d_out;

    init_state_kernel<<<(BDIM * HID + 255) / 256, 256>>>();

    {   // encoder x-projection: [8192 x 2048] @ [2048 x 2048] + b_enc
        dim3 grid(G4 / 128, (BDIM * TENC) / 128);
        gemm_kernel<0><<<grid, 256>>>(frames, W_enc, b_enc, 0, 0,
                                      BDIM * TENC, G4, DIN);
    }
    {   // decoder x-projection with gather: [4096 x 300] @ [300 x 2048] + b_dec
        dim3 grid(G4 / 128, (BDIM * TDEC) / 128);
        gemm_kernel<1><<<grid, 256>>>(emb, W_dec, b_dec, 0, cap_ids,
                                      BDIM * TDEC, G4, DW);
    }

    dim3 gs(4, 32);
    const float* WhE = W_enc + (long)DIN * G4;   // h-part rows of W_enc
    const float* WhD = W_dec + (long)DW * G4;    // h-part rows of W_dec
    for (int t = 0; t < TENC; t++)
        lstm_step_kernel<<<gs, 256>>>(0, t, t, WhE);
    for (int t = 0; t < TDEC; t++)
        lstm_step_kernel<<<gs, 256>>>(1, t, TENC + t, WhD);

    {   // output projection: [4096 x 512] @ [512 x 300] + b_out
        dim3 grid((DW + 127) / 128, (BDIM * TDEC) / 128);
        gemm_kernel<2><<<grid, 256>>>(0, W_out, b_out, out, 0,
                                      BDIM * TDEC, DW, HID);
    }
}

// round 8
// speedup vs baseline: 1.0248x; 1.0248x over previous
#include <cuda_runtime.h>
#include <math.h>

#define BDIM   128
#define TENC   64
#define TDEC   32
#define DIN    2048
#define DW     300
#define HID    512
#define G4     2048   // 4*HID

typedef unsigned long long u64;

// ---------------- scratch (device globals: no allocation allowed) -------------
// These symbols are ONLY referenced from device code. Passing them as kernel
// arguments from host code yields the HOST shadow address (silently "valid"
// over ATS on GB300) -> wrong-memory writes. Never pass them from host.
__device__ float g_pre_enc[BDIM * TENC * G4];   // [b*TENC + t][4H]  64 MB
__device__ float g_pre_dec[BDIM * TDEC * G4];   // [b*TDEC + t][4H]  32 MB
__device__ float g_h[2][BDIM * HID];            // ping-pong hidden state
__device__ float g_c[BDIM * HID];               // cell state (in-place)
__device__ float g_dechs[TDEC * BDIM * HID];    // decoder h outputs [t][b][h]

__device__ __forceinline__ float sigm(float x) { return 1.0f / (1.0f + expf(-x)); }

// packed fp32x2 FMA (PTX-only; ptxas never auto-fuses)
__device__ __forceinline__ u64 ffma2(u64 a, u64 b, u64 c) {
    u64 d;
    asm("fma.rn.f32x2 %0, %1, %2, %3;" : "=l"(d) : "l"(a), "l"(b), "l"(c));
    return d;
}

// ---------------- init: zero h0 / c0 each replay ------------------------------
__global__ void init_state_kernel() {
    int i = blockIdx.x * blockDim.x + threadIdx.x;
    if (i < BDIM * HID) {
        g_h[0][i] = 0.0f;
        g_c[i] = 0.0f;
    }
}

// ---------------- packed-f32x2 tiled GEMM:  C = A @ W + bias ------------------
// 128x128 tile, BK=8, 256 threads; per-thread 8 rows x 4 column-PAIRS (8 cols).
// Column pair p = tc + 16*j  ->  output cols n = bn0 + 2p, 2p+1.
// MODE 0: A = frames [8192 x 2048]      -> writes g_pre_enc (symbol)
// MODE 1: A-row = emb[ids[m]] (K=300)   -> writes g_pre_dec (symbol)
// MODE 2: A = g_dechs (symbol) [4096 x 512], N=300 -> writes Cout (d_out),
//         row m=(t*128+b) stored at Cout[(b*TDEC + t)*300 + n]
template <int MODE>
__global__ __launch_bounds__(256, 2)
void gemm_kernel(const float* __restrict__ A, const float* __restrict__ W,
                 const float* __restrict__ bias, float* __restrict__ Cout,
                 const int* __restrict__ ids, int M, int N, int K)
{
    __shared__ float2 As2[8][128];   // [k][m]  values duplicated (a,a)
    __shared__ float  Bs[8][128];    // [k][n]

    float* C;
    if (MODE == 0)      C = g_pre_enc;
    else if (MODE == 1) C = g_pre_dec;
    else                C = Cout;

    const int bn0 = blockIdx.x * 128;
    const int bm0 = blockIdx.y * 128;
    const int tid = threadIdx.x;

    const int arow = tid >> 1;          // 0..127
    const int ak   = (tid & 1) * 4;     // 0 or 4
    const int bk   = tid >> 5;          // 0..7
    const int bn   = (tid & 31) * 4;    // 0..124

    const float* arow_ptr;
    if (MODE == 1) {
        arow_ptr = A + (long)ids[bm0 + arow] * K;     // embedding gather
    } else if (MODE == 2) {
        arow_ptr = g_dechs + (long)(bm0 + arow) * K;
    } else {
        arow_ptr = A + (long)(bm0 + arow) * K;
    }

    const int tc = tid & 15;            // column-pair group 0..15
    const int tr = tid >> 4;            // row group         0..15

    u64 acc[8][4];
    #pragma unroll
    for (int i = 0; i < 8; i++)
        #pragma unroll
        for (int j = 0; j < 4; j++) acc[i][j] = 0ull;

    for (int kt = 0; kt < K; kt += 8) {
        #pragma unroll
        for (int s = 0; s < 4; s++) {
            int k = kt + ak + s;
            float v = (k < K) ? arow_ptr[k] : 0.0f;
            As2[ak + s][arow] = make_float2(v, v);
        }
        #pragma unroll
        for (int s = 0; s < 4; s++) {
            int k = kt + bk;
            int col = bn0 + bn + s;
            Bs[bk][bn + s] = (k < K && col < N) ? W[(long)k * N + col] : 0.0f;
        }
        __syncthreads();

        #pragma unroll
        for (int k = 0; k < 8; k++) {
            u64 a2[8], b2[4];
            const u64* ap = reinterpret_cast<const u64*>(&As2[k][0]);
            #pragma unroll
            for (int i = 0; i < 8; i++) a2[i] = ap[tr * 8 + i];
            const u64* bp = reinterpret_cast<const u64*>(&Bs[k][0]);
            #pragma unroll
            for (int j = 0; j < 4; j++) b2[j] = bp[tc + 16 * j];  // lane-consec, no conflicts
            #pragma unroll
            for (int i = 0; i < 8; i++)
                #pragma unroll
                for (int j = 0; j < 4; j++)
                    acc[i][j] = ffma2(a2[i], b2[j], acc[i][j]);
        }
        __syncthreads();
    }

    #pragma unroll
    for (int i = 0; i < 8; i++) {
        int m = bm0 + tr * 8 + i;
        #pragma unroll
        for (int j = 0; j < 4; j++) {
            float2 v = *reinterpret_cast<float2*>(&acc[i][j]);
            int n = bn0 + 2 * (tc + 16 * j);
            if (MODE == 2) {
                int b = m & 127, t = m >> 7;    // m = t*128 + b
                long obase = ((long)b * TDEC + t) * (long)N;
                if (n < N)     C[obase + n]     = v.x + bias[n];
                if (n + 1 < N) C[obase + n + 1] = v.y + bias[n + 1];
            } else {
                float* cp = C + (long)m * N + n;
                cp[0] = v.x + bias[n];
                cp[1] = v.y + bias[n + 1];
            }
        }
    }
}

// ---------------- fused recurrent LSTM step (batch-packed f32x2) --------------
// gates[b][g*512+j] = pre[b][t][g*512+j] + sum_k h[b][k]*Wh[k][g*512+j]
// Block tile: 32 b (as 16 packed pairs (b, b+16)) x 16 j x 4 gates.
// 256 threads = 16 bq x 16 jj; grid (4, 32) = 128 blocks. K-tile 32.
__global__ __launch_bounds__(256, 2)
void lstm_step_kernel(int phase /*0=enc,1=dec*/, int t, int s,
                      const float* __restrict__ Wh)
{
    __shared__ float2 hs2[16][32];   // [bq][k]: (h[b0+bq][k], h[b0+bq+16][k])
    __shared__ float2 Ws2[32][64];   // [k][g*16+jj]: (w, w) duplicated

    const float* pre = phase ? g_pre_dec : g_pre_enc;
    const int Tdim = phase ? TDEC : TENC;
    const float* hin = g_h[s & 1];
    float* hout = g_h[(s + 1) & 1];
    float* dechs = phase ? (g_dechs + (long)t * BDIM * HID) : (float*)0;

    const int tid = threadIdx.x;
    const int b0 = blockIdx.x * 32;
    const int j0 = blockIdx.y * 16;

    // loader roles
    const int hk = tid & 31;           // k within tile 0..31
    const int hb = tid >> 5;           // bq 0..7 (also loads hb+8)
    const int wq = tid & 15;           // col-within-gate 0..15
    const int wk = tid >> 4;           // k 0..15 (also loads wk+16)

    // compute roles
    const int jj = tid & 15;
    const int bq = tid >> 4;           // 0..15 (b pair: b0+bq, b0+bq+16)

    u64 acc2[4] = {0ull, 0ull, 0ull, 0ull};   // 4 gates, packed over (b, b+16)

    for (int k0 = 0; k0 < HID; k0 += 32) {
        // h tile: 16 pairs x 32 k (LDG lane-consecutive over k)
        #pragma unroll
        for (int bb = 0; bb < 2; bb++) {
            int bql = hb + bb * 8;
            float lo = hin[(long)(b0 + bql) * HID + k0 + hk];
            float hi = hin[(long)(b0 + bql + 16) * HID + k0 + hk];
            hs2[bql][hk] = make_float2(lo, hi);
        }
        // w tile: 32 k x 64 cols, duplicated pairs
        #pragma unroll
        for (int kk = 0; kk < 2; kk++) {
            int kl = wk + kk * 16;
            #pragma unroll
            for (int g = 0; g < 4; g++) {
                float w = Wh[(long)(k0 + kl) * G4 + g * HID + j0 + wq];
                Ws2[kl][g * 16 + wq] = make_float2(w, w);
            }
        }
        __syncthreads();

        #pragma unroll
        for (int k = 0; k < 32; k++) {
            u64 h2 = *reinterpret_cast<const u64*>(&hs2[bq][k]);
            #pragma unroll
            for (int g = 0; g < 4; g++) {
                u64 w2 = *reinterpret_cast<const u64*>(&Ws2[k][g * 16 + jj]);
                acc2[g] = ffma2(h2, w2, acc2[g]);
            }
        }
        __syncthreads();
    }

    float2 av[4];
    #pragma unroll
    for (int g = 0; g < 4; g++) av[g] = *reinterpret_cast<float2*>(&acc2[g]);

    #pragma unroll
    for (int bl = 0; bl < 2; bl++) {
        int b = b0 + bq + bl * 16;
        int j = j0 + jj;
        const float* pr = pre + ((long)b * Tdim + t) * G4 + j;
        float gi = (bl ? av[0].y : av[0].x) + pr[0];
        float gj = (bl ? av[1].y : av[1].x) + pr[512];
        float gf = (bl ? av[2].y : av[2].x) + pr[1024];
        float go = (bl ? av[3].y : av[3].x) + pr[1536];
        int idx = b * HID + j;
        float cn = g_c[idx] * sigm(gf + 1.0f) + sigm(gi) * tanhf(gj);
        g_c[idx] = cn;
        float hn = tanhf(cn) * sigm(go);
        hout[idx] = hn;
        if (dechs) dechs[idx] = hn;
    }
}

// ---------------- launch ------------------------------------------------------
extern "C" void kernel_launch(void* const* d_in, const int* in_sizes, int n_in,
                              void* d_out, int out_size) {
    (void)out_size;
    const float* frames  = 0;   // 16777216
    const int*   cap_ids = 0;   // 4096
    const float* emb     = 0;   // 9600000
    const float* W_enc   = 0;   // 5242880
    const float* b_enc   = 0;   // 2048 (first seen)
    const float* W_dec   = 0;   // 1662976
    const float* b_dec   = 0;   // 2048 (second seen)
    const float* W_out   = 0;   // 153600
    const float* b_out   = 0;   // 300

    for (int i = 0; i < n_in; i++) {
        long sz = in_sizes[i];
        const void* p = d_in[i];
        if      (sz == 16777216) frames  = (const float*)p;
        else if (sz == 4096)     cap_ids = (const int*)p;
        else if (sz == 9600000)  emb     = (const float*)p;
        else if (sz == 5242880)  W_enc   = (const float*)p;
        else if (sz == 1662976)  W_dec   = (const float*)p;
        else if (sz == 153600)   W_out   = (const float*)p;
        else if (sz == 300)      b_out   = (const float*)p;
        else if (sz == 2048) {
            if (!b_enc) b_enc = (const float*)p;
            else        b_dec = (const float*)p;
        }
    }
    if (!frames || !cap_ids || !emb || !W_enc || !b_enc || !W_dec || !b_dec ||
        !W_out || !b_out) {
        frames  = (const float*)d_in[0];
        cap_ids = (const int*)  d_in[1];
        emb     = (const float*)d_in[2];
        W_enc   = (const float*)d_in[3];
        b_enc   = (const float*)d_in[4];
        W_dec   = (const float*)d_in[5];
        b_dec   = (const float*)d_in[6];
        W_out   = (const float*)d_in[7];
        b_out   = (const float*)d_in[8];
    }
    float* out = (float*)d_out;

    init_state_kernel<<<(BDIM * HID + 255) / 256, 256>>>();

    {   // encoder x-projection: [8192 x 2048] @ [2048 x 2048] + b_enc
        dim3 grid(G4 / 128, (BDIM * TENC) / 128);
        gemm_kernel<0><<<grid, 256>>>(frames, W_enc, b_enc, 0, 0,
                                      BDIM * TENC, G4, DIN);
    }
    {   // decoder x-projection with gather: [4096 x 300] @ [300 x 2048] + b_dec
        dim3 grid(G4 / 128, (BDIM * TDEC) / 128);
        gemm_kernel<1><<<grid, 256>>>(emb, W_dec, b_dec, 0, cap_ids,
                                      BDIM * TDEC, G4, DW);
    }

    dim3 gs(4, 32);
    const float* WhE = W_enc + (long)DIN * G4;   // h-part rows of W_enc
    const float* WhD = W_dec + (long)DW * G4;    // h-part rows of W_dec
    for (int t = 0; t < TENC; t++)
        lstm_step_kernel<<<gs, 256>>>(0, t, t, WhE);
    for (int t = 0; t < TDEC; t++)
        lstm_step_kernel<<<gs, 256>>>(1, t, TENC + t, WhD);

    {   // output projection: [4096 x 512] @ [512 x 300] + b_out
        dim3 grid((DW + 127) / 128, (BDIM * TDEC) / 128);
        gemm_kernel<2><<<grid, 256>>>(0, W_out, b_out, out, 0,
                                      BDIM * TDEC, DW, HID);
    }
}

// round 9
// speedup vs baseline: 1.3404x; 1.3080x over previous
#include <cuda_runtime.h>
#include <math.h>

#define BDIM   128
#define TENC   64
#define TDEC   32
#define DIN    2048
#define DW     300
#define HID    512
#define G4     2048   // 4*HID

typedef unsigned long long u64;

// ---------------- scratch (device globals: no allocation allowed) -------------
// These symbols are ONLY referenced from device code. Passing them as kernel
// arguments from host code yields the HOST shadow address (silently "valid"
// over ATS on GB300) -> wrong-memory writes. Never pass them from host.
__device__ float g_pre_enc[BDIM * TENC * G4];   // [b*TENC + t][4H]  64 MB
__device__ float g_pre_dec[BDIM * TDEC * G4];   // [b*TDEC + t][4H]  32 MB
__device__ float g_h[2][BDIM * HID];            // ping-pong hidden state
__device__ float g_c[BDIM * HID];               // cell state (in-place)
__device__ float g_dechs[TDEC * BDIM * HID];    // decoder h outputs [t][b][h]

__device__ __forceinline__ float sigm(float x) { return 1.0f / (1.0f + expf(-x)); }

// packed fp32x2 FMA (PTX-only; ptxas never auto-fuses)
__device__ __forceinline__ u64 ffma2(u64 a, u64 b, u64 c) {
    u64 d;
    asm("fma.rn.f32x2 %0, %1, %2, %3;" : "=l"(d) : "l"(a), "l"(b), "l"(c));
    return d;
}
// duplicate scalar into packed pair IN REGISTERS (ALU pipe, not crossbar)
__device__ __forceinline__ u64 dup2(float w) {
    u64 d;
    asm("mov.b64 %0, {%1, %1};" : "=l"(d) : "f"(w));
    return d;
}

// ---------------- init: zero h0 / c0 each replay ------------------------------
__global__ void init_state_kernel() {
    int i = blockIdx.x * blockDim.x + threadIdx.x;
    if (i < BDIM * HID) {
        g_h[0][i] = 0.0f;
        g_c[i] = 0.0f;
    }
}

// ---------------- packed-f32x2 tiled GEMM:  C = A @ W + bias ------------------
// 128x128 tile, BK=8, 256 threads; per-thread 8 rows x 4 column-PAIRS (8 cols).
// A tile stored SCALAR (vector LDS.128 reads + in-register dup) to minimize
// smem crossbar bytes: 64 B/thread/k for 64 MACs.
// MODE 0: A = frames [8192 x 2048]      -> writes g_pre_enc (symbol)
// MODE 1: A-row = emb[ids[m]] (K=300)   -> writes g_pre_dec (symbol)
// MODE 2: A = g_dechs (symbol) [4096 x 512], N=300 -> writes Cout (d_out),
//         row m=(t*128+b) stored at Cout[(b*TDEC + t)*300 + n]
template <int MODE>
__global__ __launch_bounds__(256, 2)
void gemm_kernel(const float* __restrict__ A, const float* __restrict__ W,
                 const float* __restrict__ bias, float* __restrict__ Cout,
                 const int* __restrict__ ids, int M, int N, int K)
{
    __shared__ float As[8][132];   // [k][m] scalar, padded (132*4B = 33*16B rows)
    __shared__ float Bs[8][128];   // [k][n]

    float* C;
    if (MODE == 0)      C = g_pre_enc;
    else if (MODE == 1) C = g_pre_dec;
    else                C = Cout;

    const int bn0 = blockIdx.x * 128;
    const int bm0 = blockIdx.y * 128;
    const int tid = threadIdx.x;

    const int arow = tid >> 1;          // 0..127
    const int ak   = (tid & 1) * 4;     // 0 or 4
    const int bk   = tid >> 5;          // 0..7
    const int bn   = (tid & 31) * 4;    // 0..124

    const float* arow_ptr;
    if (MODE == 1) {
        arow_ptr = A + (long)ids[bm0 + arow] * K;     // embedding gather
    } else if (MODE == 2) {
        arow_ptr = g_dechs + (long)(bm0 + arow) * K;
    } else {
        arow_ptr = A + (long)(bm0 + arow) * K;
    }

    const int tc = tid & 15;            // column-pair group 0..15
    const int tr = tid >> 4;            // row group         0..15

    u64 acc[8][4];
    #pragma unroll
    for (int i = 0; i < 8; i++)
        #pragma unroll
        for (int j = 0; j < 4; j++) acc[i][j] = 0ull;

    for (int kt = 0; kt < K; kt += 8) {
        #pragma unroll
        for (int s = 0; s < 4; s++) {
            int k = kt + ak + s;
            As[ak + s][arow] = (k < K) ? arow_ptr[k] : 0.0f;
        }
        #pragma unroll
        for (int s = 0; s < 4; s++) {
            int k = kt + bk;
            int col = bn0 + bn + s;
            Bs[bk][bn + s] = (k < K && col < N) ? W[(long)k * N + col] : 0.0f;
        }
        __syncthreads();

        #pragma unroll
        for (int k = 0; k < 8; k++) {
            // A: 8 consecutive scalars via 2x LDS.128, duplicate in registers
            float4 a0 = *reinterpret_cast<const float4*>(&As[k][tr * 8]);
            float4 a1 = *reinterpret_cast<const float4*>(&As[k][tr * 8 + 4]);
            u64 a2[8];
            a2[0] = dup2(a0.x); a2[1] = dup2(a0.y);
            a2[2] = dup2(a0.z); a2[3] = dup2(a0.w);
            a2[4] = dup2(a1.x); a2[5] = dup2(a1.y);
            a2[6] = dup2(a1.z); a2[7] = dup2(a1.w);
            // B: 4 lane-consecutive u64 pairs
            const u64* bp = reinterpret_cast<const u64*>(&Bs[k][0]);
            u64 b2[4];
            #pragma unroll
            for (int j = 0; j < 4; j++) b2[j] = bp[tc + 16 * j];
            #pragma unroll
            for (int i = 0; i < 8; i++)
                #pragma unroll
                for (int j = 0; j < 4; j++)
                    acc[i][j] = ffma2(a2[i], b2[j], acc[i][j]);
        }
        __syncthreads();
    }

    #pragma unroll
    for (int i = 0; i < 8; i++) {
        int m = bm0 + tr * 8 + i;
        #pragma unroll
        for (int j = 0; j < 4; j++) {
            float2 v = *reinterpret_cast<float2*>(&acc[i][j]);
            int n = bn0 + 2 * (tc + 16 * j);
            if (MODE == 2) {
                int b = m & 127, t = m >> 7;    // m = t*128 + b
                long obase = ((long)b * TDEC + t) * (long)N;
                if (n < N)     C[obase + n]     = v.x + bias[n];
                if (n + 1 < N) C[obase + n + 1] = v.y + bias[n + 1];
            } else {
                float* cp = C + (long)m * N + n;
                cp[0] = v.x + bias[n];
                cp[1] = v.y + bias[n + 1];
            }
        }
    }
}

// ---------------- fused recurrent LSTM step (batch-packed f32x2) --------------
// gates[b][g*512+j] = pre[b][t][g*512+j] + sum_k h[b][k]*Wh[k][g*512+j]
// Block tile: 32 b (16 packed pairs (b,b+16)) x 16 j x 4 gates; 256 threads.
// Weight tile stored SCALAR gate-transposed: Ws[k][jj*4+g] -> one LDS.128
// fetches all 4 gate weights; duplication happens in registers.
// Inner k: 1 LDS.64 (h-pair) + 1 LDS.128 (4 w) + 4 dup + 4 ffma2.
__global__ __launch_bounds__(256, 2)
void lstm_step_kernel(int phase /*0=enc,1=dec*/, int t, int s,
                      const float* __restrict__ Wh)
{
    __shared__ float2 hs2[16][33];   // [bq][k] padded: (h[b0+bq][k], h[b0+bq+16][k])
    __shared__ float  Ws[32][68];    // [k][jj*4+g] padded (68*4B = 17*16B rows)

    const float* pre = phase ? g_pre_dec : g_pre_enc;
    const int Tdim = phase ? TDEC : TENC;
    const float* hin = g_h[s & 1];
    float* hout = g_h[(s + 1) & 1];
    float* dechs = phase ? (g_dechs + (long)t * BDIM * HID) : (float*)0;

    const int tid = threadIdx.x;
    const int b0 = blockIdx.x * 32;
    const int j0 = blockIdx.y * 16;

    // loader roles
    const int hk = tid & 31;           // k within tile 0..31
    const int hb = tid >> 5;           // bq 0..7 (also loads hb+8)
    const int wq = tid & 15;           // column-within-tile 0..15
    const int wk = tid >> 4;           // k 0..15 (also loads wk+16)

    // compute roles
    const int jj = tid & 15;
    const int bq = tid >> 4;           // 0..15 (b pair: b0+bq, b0+bq+16)

    u64 acc2[4] = {0ull, 0ull, 0ull, 0ull};   // 4 gates, packed over (b, b+16)

    for (int k0 = 0; k0 < HID; k0 += 32) {
        // h tile: 16 pairs x 32 k (coalesced LDG over k)
        #pragma unroll
        for (int bb = 0; bb < 2; bb++) {
            int bql = hb + bb * 8;
            float lo = hin[(long)(b0 + bql) * HID + k0 + hk];
            float hi = hin[(long)(b0 + bql + 16) * HID + k0 + hk];
            hs2[bql][hk] = make_float2(lo, hi);
        }
        // w tile: gate-transposed scalar; one float4 store per (k, column)
        #pragma unroll
        for (int kk = 0; kk < 2; kk++) {
            int kl = wk + kk * 16;
            const float* wp = Wh + (long)(k0 + kl) * G4 + j0 + wq;
            float4 wv = make_float4(wp[0], wp[512], wp[1024], wp[1536]);
            *reinterpret_cast<float4*>(&Ws[kl][wq * 4]) = wv;
        }
        __syncthreads();

        #pragma unroll
        for (int k = 0; k < 32; k++) {
            u64 h2 = *reinterpret_cast<const u64*>(&hs2[bq][k]);
            float4 wv = *reinterpret_cast<const float4*>(&Ws[k][jj * 4]);
            acc2[0] = ffma2(h2, dup2(wv.x), acc2[0]);
            acc2[1] = ffma2(h2, dup2(wv.y), acc2[1]);
            acc2[2] = ffma2(h2, dup2(wv.z), acc2[2]);
            acc2[3] = ffma2(h2, dup2(wv.w), acc2[3]);
        }
        __syncthreads();
    }

    float2 av[4];
    #pragma unroll
    for (int g = 0; g < 4; g++) av[g] = *reinterpret_cast<float2*>(&acc2[g]);

    #pragma unroll
    for (int bl = 0; bl < 2; bl++) {
        int b = b0 + bq + bl * 16;
        int j = j0 + jj;
        const float* pr = pre + ((long)b * Tdim + t) * G4 + j;
        float gi = (bl ? av[0].y : av[0].x) + pr[0];
        float gj = (bl ? av[1].y : av[1].x) + pr[512];
        float gf = (bl ? av[2].y : av[2].x) + pr[1024];
        float go = (bl ? av[3].y : av[3].x) + pr[1536];
        int idx = b * HID + j;
        float cn = g_c[idx] * sigm(gf + 1.0f) + sigm(gi) * tanhf(gj);
        g_c[idx] = cn;
        float hn = tanhf(cn) * sigm(go);
        hout[idx] = hn;
        if (dechs) dechs[idx] = hn;
    }
}

// ---------------- launch ------------------------------------------------------
extern "C" void kernel_launch(void* const* d_in, const int* in_sizes, int n_in,
                              void* d_out, int out_size) {
    (void)out_size;
    const float* frames  = 0;   // 16777216
    const int*   cap_ids = 0;   // 4096
    const float* emb     = 0;   // 9600000
    const float* W_enc   = 0;   // 5242880
    const float* b_enc   = 0;   // 2048 (first seen)
    const float* W_dec   = 0;   // 1662976
    const float* b_dec   = 0;   // 2048 (second seen)
    const float* W_out   = 0;   // 153600
    const float* b_out   = 0;   // 300

    for (int i = 0; i < n_in; i++) {
        long sz = in_sizes[i];
        const void* p = d_in[i];
        if      (sz == 16777216) frames  = (const float*)p;
        else if (sz == 4096)     cap_ids = (const int*)p;
        else if (sz == 9600000)  emb     = (const float*)p;
        else if (sz == 5242880)  W_enc   = (const float*)p;
        else if (sz == 1662976)  W_dec   = (const float*)p;
        else if (sz == 153600)   W_out   = (const float*)p;
        else if (sz == 300)      b_out   = (const float*)p;
        else if (sz == 2048) {
            if (!b_enc) b_enc = (const float*)p;
            else        b_dec = (const float*)p;
        }
    }
    if (!frames || !cap_ids || !emb || !W_enc || !b_enc || !W_dec || !b_dec ||
        !W_out || !b_out) {
        frames  = (const float*)d_in[0];
        cap_ids = (const int*)  d_in[1];
        emb     = (const float*)d_in[2];
        W_enc   = (const float*)d_in[3];
        b_enc   = (const float*)d_in[4];
        W_dec   = (const float*)d_in[5];
        b_dec   = (const float*)d_in[6];
        W_out   = (const float*)d_in[7];
        b_out   = (const float*)d_in[8];
    }
    float* out = (float*)d_out;

    init_state_kernel<<<(BDIM * HID + 255) / 256, 256>>>();

    {   // encoder x-projection: [8192 x 2048] @ [2048 x 2048] + b_enc
        dim3 grid(G4 / 128, (BDIM * TENC) / 128);
        gemm_kernel<0><<<grid, 256>>>(frames, W_enc, b_enc, 0, 0,
                                      BDIM * TENC, G4, DIN);
    }
    {   // decoder x-projection with gather: [4096 x 300] @ [300 x 2048] + b_dec
        dim3 grid(G4 / 128, (BDIM * TDEC) / 128);
        gemm_kernel<1><<<grid, 256>>>(emb, W_dec, b_dec, 0, cap_ids,
                                      BDIM * TDEC, G4, DW);
    }

    dim3 gs(4, 32);
    const float* WhE = W_enc + (long)DIN * G4;   // h-part rows of W_enc
    const float* WhD = W_dec + (long)DW * G4;    // h-part rows of W_dec
    for (int t = 0; t < TENC; t++)
        lstm_step_kernel<<<gs, 256>>>(0, t, t, WhE);
    for (int t = 0; t < TDEC; t++)
        lstm_step_kernel<<<gs, 256>>>(1, t, TENC + t, WhD);

    {   // output projection: [4096 x 512] @ [512 x 300] + b_out
        dim3 grid((DW + 127) / 128, (BDIM * TDEC) / 128);
        gemm_kernel<2><<<grid, 256>>>(0, W_out, b_out, out, 0,
                                      BDIM * TDEC, DW, HID);
    }
}

// round 10
// speedup vs baseline: 1.4052x; 1.0483x over previous
#include <cuda_runtime.h>
#include <math.h>

#define BDIM   128
#define TENC   64
#define TDEC   32
#define DIN    2048
#define DW     300
#define HID    512
#define G4     2048   // 4*HID

typedef unsigned long long u64;

// ---------------- scratch (device globals: no allocation allowed) -------------
// These symbols are ONLY referenced from device code. Passing them as kernel
// arguments from host code yields the HOST shadow address (silently "valid"
// over ATS on GB300) -> wrong-memory writes. Never pass them from host.
__device__ float g_pre_enc[BDIM * TENC * G4];   // [b*TENC + t][4H]  64 MB
__device__ float g_pre_dec[BDIM * TDEC * G4];   // [b*TDEC + t][4H]  32 MB
__device__ float g_h[2][BDIM * HID];            // ping-pong hidden state
__device__ float g_c[BDIM * HID];               // cell state (in-place)
__device__ float g_dechs[TDEC * BDIM * HID];    // decoder h outputs [t][b][h]

__device__ __forceinline__ float sigm(float x) { return 1.0f / (1.0f + expf(-x)); }

// packed fp32x2 FMA / ADD (PTX-only; ptxas never auto-fuses)
__device__ __forceinline__ u64 ffma2(u64 a, u64 b, u64 c) {
    u64 d;
    asm("fma.rn.f32x2 %0, %1, %2, %3;" : "=l"(d) : "l"(a), "l"(b), "l"(c));
    return d;
}
__device__ __forceinline__ u64 fadd2(u64 a, u64 b) {
    u64 d;
    asm("add.rn.f32x2 %0, %1, %2;" : "=l"(d) : "l"(a), "l"(b));
    return d;
}
// duplicate scalar into packed pair IN REGISTERS (ALU pipe, not crossbar)
__device__ __forceinline__ u64 dup2(float w) {
    u64 d;
    asm("mov.b64 %0, {%1, %1};" : "=l"(d) : "f"(w));
    return d;
}

// ---------------- init: zero h0 / c0 each replay ------------------------------
__global__ void init_state_kernel() {
    int i = blockIdx.x * blockDim.x + threadIdx.x;
    if (i < BDIM * HID) {
        g_h[0][i] = 0.0f;
        g_c[i] = 0.0f;
    }
}

// ---------------- packed-f32x2 tiled GEMM:  C = A @ W + bias ------------------
// (unchanged from R9 — near f32x2 roofline)
template <int MODE>
__global__ __launch_bounds__(256, 2)
void gemm_kernel(const float* __restrict__ A, const float* __restrict__ W,
                 const float* __restrict__ bias, float* __restrict__ Cout,
                 const int* __restrict__ ids, int M, int N, int K)
{
    __shared__ float As[8][132];   // [k][m] scalar, padded
    __shared__ float Bs[8][128];   // [k][n]

    float* C;
    if (MODE == 0)      C = g_pre_enc;
    else if (MODE == 1) C = g_pre_dec;
    else                C = Cout;

    const int bn0 = blockIdx.x * 128;
    const int bm0 = blockIdx.y * 128;
    const int tid = threadIdx.x;

    const int arow = tid >> 1;          // 0..127
    const int ak   = (tid & 1) * 4;     // 0 or 4
    const int bk   = tid >> 5;          // 0..7
    const int bn   = (tid & 31) * 4;    // 0..124

    const float* arow_ptr;
    if (MODE == 1) {
        arow_ptr = A + (long)ids[bm0 + arow] * K;     // embedding gather
    } else if (MODE == 2) {
        arow_ptr = g_dechs + (long)(bm0 + arow) * K;
    } else {
        arow_ptr = A + (long)(bm0 + arow) * K;
    }

    const int tc = tid & 15;            // column-pair group 0..15
    const int tr = tid >> 4;            // row group         0..15

    u64 acc[8][4];
    #pragma unroll
    for (int i = 0; i < 8; i++)
        #pragma unroll
        for (int j = 0; j < 4; j++) acc[i][j] = 0ull;

    for (int kt = 0; kt < K; kt += 8) {
        #pragma unroll
        for (int s = 0; s < 4; s++) {
            int k = kt + ak + s;
            As[ak + s][arow] = (k < K) ? arow_ptr[k] : 0.0f;
        }
        #pragma unroll
        for (int s = 0; s < 4; s++) {
            int k = kt + bk;
            int col = bn0 + bn + s;
            Bs[bk][bn + s] = (k < K && col < N) ? W[(long)k * N + col] : 0.0f;
        }
        __syncthreads();

        #pragma unroll
        for (int k = 0; k < 8; k++) {
            float4 a0 = *reinterpret_cast<const float4*>(&As[k][tr * 8]);
            float4 a1 = *reinterpret_cast<const float4*>(&As[k][tr * 8 + 4]);
            u64 a2[8];
            a2[0] = dup2(a0.x); a2[1] = dup2(a0.y);
            a2[2] = dup2(a0.z); a2[3] = dup2(a0.w);
            a2[4] = dup2(a1.x); a2[5] = dup2(a1.y);
            a2[6] = dup2(a1.z); a2[7] = dup2(a1.w);
            const u64* bp = reinterpret_cast<const u64*>(&Bs[k][0]);
            u64 b2[4];
            #pragma unroll
            for (int j = 0; j < 4; j++) b2[j] = bp[tc + 16 * j];
            #pragma unroll
            for (int i = 0; i < 8; i++)
                #pragma unroll
                for (int j = 0; j < 4; j++)
                    acc[i][j] = ffma2(a2[i], b2[j], acc[i][j]);
        }
        __syncthreads();
    }

    #pragma unroll
    for (int i = 0; i < 8; i++) {
        int m = bm0 + tr * 8 + i;
        #pragma unroll
        for (int j = 0; j < 4; j++) {
            float2 v = *reinterpret_cast<float2*>(&acc[i][j]);
            int n = bn0 + 2 * (tc + 16 * j);
            if (MODE == 2) {
                int b = m & 127, t = m >> 7;    // m = t*128 + b
                long obase = ((long)b * TDEC + t) * (long)N;
                if (n < N)     C[obase + n]     = v.x + bias[n];
                if (n + 1 < N) C[obase + n + 1] = v.y + bias[n + 1];
            } else {
                float* cp = C + (long)m * N + n;
                cp[0] = v.x + bias[n];
                cp[1] = v.y + bias[n + 1];
            }
        }
    }
}

// ---------------- fused recurrent LSTM step (split-K, 512 threads) ------------
// gates[b][g*512+j] = pre[b][t][g*512+j] + sum_k h[b][k]*Wh[k][g*512+j]
// Block tile: 32 b (16 packed pairs (b,b+16)) x 16 j x 4 gates.
// 512 threads = 2 k-halves x 256; half 0: k in [0,256), half 1: k in [256,512).
// Each half uses the R9 tile geometry on its k-range; partials reduced via
// smem, half 0 runs the pointwise epilogue. grid (4, 32) = 128 blocks.
__global__ __launch_bounds__(512, 1)
void lstm_step_kernel(int phase /*0=enc,1=dec*/, int t, int s,
                      const float* __restrict__ Wh)
{
    __shared__ float2 hs2[2][16][33];  // [half][bq][k] padded
    __shared__ float  Ws[2][32][68];   // [half][k][jj*4+g] padded
    __shared__ u64    red[256][4];     // half-1 partials

    const float* pre = phase ? g_pre_dec : g_pre_enc;
    const int Tdim = phase ? TDEC : TENC;
    const float* hin = g_h[s & 1];
    float* hout = g_h[(s + 1) & 1];
    float* dechs = phase ? (g_dechs + (long)t * BDIM * HID) : (float*)0;

    const int tid  = threadIdx.x;
    const int half = tid >> 8;          // 0 or 1
    const int ltid = tid & 255;
    const int kbase = half << 8;        // 0 or 256
    const int b0 = blockIdx.x * 32;
    const int j0 = blockIdx.y * 16;

    // loader roles (within half)
    const int hk = ltid & 31;           // k within tile 0..31
    const int hb = ltid >> 5;           // bq 0..7 (also loads hb+8)
    const int wq = ltid & 15;           // column-within-tile 0..15
    const int wk = ltid >> 4;           // k 0..15 (also loads wk+16)

    // compute roles (within half)
    const int jj = ltid & 15;
    const int bq = ltid >> 4;           // 0..15 (b pair: b0+bq, b0+bq+16)

    u64 acc2[4] = {0ull, 0ull, 0ull, 0ull};

    #pragma unroll 1
    for (int kt = 0; kt < 8; kt++) {
        const int k0 = kbase + kt * 32;
        // h tile: 16 pairs x 32 k (coalesced LDG over k)
        #pragma unroll
        for (int bb = 0; bb < 2; bb++) {
            int bql = hb + bb * 8;
            float lo = hin[(long)(b0 + bql) * HID + k0 + hk];
            float hi = hin[(long)(b0 + bql + 16) * HID + k0 + hk];
            hs2[half][bql][hk] = make_float2(lo, hi);
        }
        // w tile: gate-transposed scalar; one float4 store per (k, column)
        #pragma unroll
        for (int kk = 0; kk < 2; kk++) {
            int kl = wk + kk * 16;
            const float* wp = Wh + (long)(k0 + kl) * G4 + j0 + wq;
            float4 wv = make_float4(wp[0], wp[512], wp[1024], wp[1536]);
            *reinterpret_cast<float4*>(&Ws[half][kl][wq * 4]) = wv;
        }
        __syncthreads();

        #pragma unroll
        for (int k = 0; k < 32; k++) {
            u64 h2 = *reinterpret_cast<const u64*>(&hs2[half][bq][k]);
            float4 wv = *reinterpret_cast<const float4*>(&Ws[half][k][jj * 4]);
            acc2[0] = ffma2(h2, dup2(wv.x), acc2[0]);
            acc2[1] = ffma2(h2, dup2(wv.y), acc2[1]);
            acc2[2] = ffma2(h2, dup2(wv.z), acc2[2]);
            acc2[3] = ffma2(h2, dup2(wv.w), acc2[3]);
        }
        __syncthreads();
    }

    // ---- cross-half reduction ----
    if (half == 1) {
        #pragma unroll
        for (int g = 0; g < 4; g++) red[ltid][g] = acc2[g];
    }
    __syncthreads();
    if (half == 0) {
        #pragma unroll
        for (int g = 0; g < 4; g++) acc2[g] = fadd2(acc2[g], red[ltid][g]);

        float2 av[4];
        #pragma unroll
        for (int g = 0; g < 4; g++) av[g] = *reinterpret_cast<float2*>(&acc2[g]);

        #pragma unroll
        for (int bl = 0; bl < 2; bl++) {
            int b = b0 + bq + bl * 16;
            int j = j0 + jj;
            const float* pr = pre + ((long)b * Tdim + t) * G4 + j;
            float gi = (bl ? av[0].y : av[0].x) + pr[0];
            float gj = (bl ? av[1].y : av[1].x) + pr[512];
            float gf = (bl ? av[2].y : av[2].x) + pr[1024];
            float go = (bl ? av[3].y : av[3].x) + pr[1536];
            int idx = b * HID + j;
            float cn = g_c[idx] * sigm(gf + 1.0f) + sigm(gi) * tanhf(gj);
            g_c[idx] = cn;
            float hn = tanhf(cn) * sigm(go);
            hout[idx] = hn;
            if (dechs) dechs[idx] = hn;
        }
    }
}

// ---------------- launch ------------------------------------------------------
extern "C" void kernel_launch(void* const* d_in, const int* in_sizes, int n_in,
                              void* d_out, int out_size) {
    (void)out_size;
    const float* frames  = 0;   // 16777216
    const int*   cap_ids = 0;   // 4096
    const float* emb     = 0;   // 9600000
    const float* W_enc   = 0;   // 5242880
    const float* b_enc   = 0;   // 2048 (first seen)
    const float* W_dec   = 0;   // 1662976
    const float* b_dec   = 0;   // 2048 (second seen)
    const float* W_out   = 0;   // 153600
    const float* b_out   = 0;   // 300

    for (int i = 0; i < n_in; i++) {
        long sz = in_sizes[i];
        const void* p = d_in[i];
        if      (sz == 16777216) frames  = (const float*)p;
        else if (sz == 4096)     cap_ids = (const int*)p;
        else if (sz == 9600000)  emb     = (const float*)p;
        else if (sz == 5242880)  W_enc   = (const float*)p;
        else if (sz == 1662976)  W_dec   = (const float*)p;
        else if (sz == 153600)   W_out   = (const float*)p;
        else if (sz == 300)      b_out   = (const float*)p;
        else if (sz == 2048) {
            if (!b_enc) b_enc = (const float*)p;
            else        b_dec = (const float*)p;
        }
    }
    if (!frames || !cap_ids || !emb || !W_enc || !b_enc || !W_dec || !b_dec ||
        !W_out || !b_out) {
        frames  = (const float*)d_in[0];
        cap_ids = (const int*)  d_in[1];
        emb     = (const float*)d_in[2];
        W_enc   = (const float*)d_in[3];
        b_enc   = (const float*)d_in[4];
        W_dec   = (const float*)d_in[5];
        b_dec   = (const float*)d_in[6];
        W_out   = (const float*)d_in[7];
        b_out   = (const float*)d_in[8];
    }
    float* out = (float*)d_out;

    init_state_kernel<<<(BDIM * HID + 255) / 256, 256>>>();

    {   // encoder x-projection: [8192 x 2048] @ [2048 x 2048] + b_enc
        dim3 grid(G4 / 128, (BDIM * TENC) / 128);
        gemm_kernel<0><<<grid, 256>>>(frames, W_enc, b_enc, 0, 0,
                                      BDIM * TENC, G4, DIN);
    }
    {   // decoder x-projection with gather: [4096 x 300] @ [300 x 2048] + b_dec
        dim3 grid(G4 / 128, (BDIM * TDEC) / 128);
        gemm_kernel<1><<<grid, 256>>>(emb, W_dec, b_dec, 0, cap_ids,
                                      BDIM * TDEC, G4, DW);
    }

    dim3 gs(4, 32);
    const float* WhE = W_enc + (long)DIN * G4;   // h-part rows of W_enc
    const float* WhD = W_dec + (long)DW * G4;    // h-part rows of W_dec
    for (int t = 0; t < TENC; t++)
        lstm_step_kernel<<<gs, 512>>>(0, t, t, WhE);
    for (int t = 0; t < TDEC; t++)
        lstm_step_kernel<<<gs, 512>>>(1, t, TENC + t, WhD);

    {   // output projection: [4096 x 512] @ [512 x 300] + b_out
        dim3 grid((DW + 127) / 128, (BDIM * TDEC) / 128);
        gemm_kernel<2><<<grid, 256>>>(0, W_out, b_out, out, 0,
                                      BDIM * TDEC, DW, HID);
    }
}

// round 11
// speedup vs baseline: 1.5466x; 1.1006x over previous
#include <cuda_runtime.h>
#include <math.h>

#define BDIM   128
#define TENC   64
#define TDEC   32
#define DIN    2048
#define DW     300
#define HID    512
#define G4     2048   // 4*HID
#define NBLK   128    // persistent grid: 4 b-groups x 32 j-groups

typedef unsigned long long u64;

// ---------------- scratch (device globals: no allocation allowed) -------------
// These symbols are ONLY referenced from device code. Passing them as kernel
// arguments from host code yields the HOST shadow address (silently "valid"
// over ATS on GB300) -> wrong-memory writes. Never pass them from host.
__device__ float g_pre_enc[BDIM * TENC * G4];   // [b*TENC + t][4H]  64 MB
__device__ float g_pre_dec[BDIM * TDEC * G4];   // [b*TDEC + t][4H]  32 MB
__device__ float g_h[2][BDIM * HID];            // ping-pong hidden state
__device__ float g_c[BDIM * HID];               // cell state (in-place)
__device__ float g_dechs[TDEC * BDIM * HID];    // decoder h outputs [t][b][h]

// grid barrier state (count invariant: returns to 0 after each barrier)
__device__ unsigned g_bar_count = 0;
__device__ volatile unsigned g_bar_gen = 0;

__device__ __forceinline__ float sigm(float x) { return 1.0f / (1.0f + expf(-x)); }

// packed fp32x2 FMA / ADD (PTX-only; ptxas never auto-fuses)
__device__ __forceinline__ u64 ffma2(u64 a, u64 b, u64 c) {
    u64 d;
    asm("fma.rn.f32x2 %0, %1, %2, %3;" : "=l"(d) : "l"(a), "l"(b), "l"(c));
    return d;
}
__device__ __forceinline__ u64 fadd2(u64 a, u64 b) {
    u64 d;
    asm("add.rn.f32x2 %0, %1, %2;" : "=l"(d) : "l"(a), "l"(b));
    return d;
}
// duplicate scalar into packed pair IN REGISTERS (ALU pipe, not crossbar)
__device__ __forceinline__ u64 dup2(float w) {
    u64 d;
    asm("mov.b64 %0, {%1, %1};" : "=l"(d) : "f"(w));
    return d;
}

// two-phase sense-reversing grid barrier; safe because all NBLK blocks are
// co-resident (1 block/SM, 128 blocks <= 148 SMs).
__device__ __forceinline__ void grid_sync() {
    __syncthreads();
    if (threadIdx.x == 0) {
        __threadfence();                      // publish this block's writes
        unsigned my = g_bar_gen;              // snapshot BEFORE arriving
        if (atomicAdd(&g_bar_count, 1) == NBLK - 1) {
            g_bar_count = 0;
            __threadfence();
            g_bar_gen = my + 1;               // release
        } else {
            while (g_bar_gen == my) { __nanosleep(32); }
        }
        __threadfence();                      // acquire
    }
    __syncthreads();
}

// ---------------- packed-f32x2 tiled GEMM:  C = A @ W + bias ------------------
// (unchanged from R10 — near f32x2 roofline)
template <int MODE>
__global__ __launch_bounds__(256, 2)
void gemm_kernel(const float* __restrict__ A, const float* __restrict__ W,
                 const float* __restrict__ bias, float* __restrict__ Cout,
                 const int* __restrict__ ids, int M, int N, int K)
{
    __shared__ float As[8][132];   // [k][m] scalar, padded
    __shared__ float Bs[8][128];   // [k][n]

    float* C;
    if (MODE == 0)      C = g_pre_enc;
    else if (MODE == 1) C = g_pre_dec;
    else                C = Cout;

    const int bn0 = blockIdx.x * 128;
    const int bm0 = blockIdx.y * 128;
    const int tid = threadIdx.x;

    const int arow = tid >> 1;          // 0..127
    const int ak   = (tid & 1) * 4;     // 0 or 4
    const int bk   = tid >> 5;          // 0..7
    const int bn   = (tid & 31) * 4;    // 0..124

    const float* arow_ptr;
    if (MODE == 1) {
        arow_ptr = A + (long)ids[bm0 + arow] * K;     // embedding gather
    } else if (MODE == 2) {
        arow_ptr = g_dechs + (long)(bm0 + arow) * K;
    } else {
        arow_ptr = A + (long)(bm0 + arow) * K;
    }

    const int tc = tid & 15;            // column-pair group 0..15
    const int tr = tid >> 4;            // row group         0..15

    u64 acc[8][4];
    #pragma unroll
    for (int i = 0; i < 8; i++)
        #pragma unroll
        for (int j = 0; j < 4; j++) acc[i][j] = 0ull;

    for (int kt = 0; kt < K; kt += 8) {
        #pragma unroll
        for (int s = 0; s < 4; s++) {
            int k = kt + ak + s;
            As[ak + s][arow] = (k < K) ? arow_ptr[k] : 0.0f;
        }
        #pragma unroll
        for (int s = 0; s < 4; s++) {
            int k = kt + bk;
            int col = bn0 + bn + s;
            Bs[bk][bn + s] = (k < K && col < N) ? W[(long)k * N + col] : 0.0f;
        }
        __syncthreads();

        #pragma unroll
        for (int k = 0; k < 8; k++) {
            float4 a0 = *reinterpret_cast<const float4*>(&As[k][tr * 8]);
            float4 a1 = *reinterpret_cast<const float4*>(&As[k][tr * 8 + 4]);
            u64 a2[8];
            a2[0] = dup2(a0.x); a2[1] = dup2(a0.y);
            a2[2] = dup2(a0.z); a2[3] = dup2(a0.w);
            a2[4] = dup2(a1.x); a2[5] = dup2(a1.y);
            a2[6] = dup2(a1.z); a2[7] = dup2(a1.w);
            const u64* bp = reinterpret_cast<const u64*>(&Bs[k][0]);
            u64 b2[4];
            #pragma unroll
            for (int j = 0; j < 4; j++) b2[j] = bp[tc + 16 * j];
            #pragma unroll
            for (int i = 0; i < 8; i++)
                #pragma unroll
                for (int j = 0; j < 4; j++)
                    acc[i][j] = ffma2(a2[i], b2[j], acc[i][j]);
        }
        __syncthreads();
    }

    #pragma unroll
    for (int i = 0; i < 8; i++) {
        int m = bm0 + tr * 8 + i;
        #pragma unroll
        for (int j = 0; j < 4; j++) {
            float2 v = *reinterpret_cast<float2*>(&acc[i][j]);
            int n = bn0 + 2 * (tc + 16 * j);
            if (MODE == 2) {
                int b = m & 127, t = m >> 7;    // m = t*128 + b
                long obase = ((long)b * TDEC + t) * (long)N;
                if (n < N)     C[obase + n]     = v.x + bias[n];
                if (n + 1 < N) C[obase + n + 1] = v.y + bias[n + 1];
            } else {
                float* cp = C + (long)m * N + n;
                cp[0] = v.x + bias[n];
                cp[1] = v.y + bias[n + 1];
            }
        }
    }
}

// ---------------- persistent recurrent LSTM (all 96 steps, one launch) --------
// Block (bg, jg): owns b0 = bg*32 (32 batches as 16 pairs (b,b+16)) and
// j0 = jg*16 (16 j-columns x 4 gates). Weights for the block's slice live in
// smem for the whole phase. 512 threads = 2 k-halves x (16 bq x 16 jj).
// Per step: grid_sync -> stage h -> FMA from smem -> reduce halves -> epilogue.
//
// Dynamic smem layout:
//   Ws   float[512][68]            139,264 B  (persistent per phase)
//   hs2  float2[16][520]            66,560 B  (per-step h staging)
//   red  u64[256][4] aliased on hs2  (used only after compute is done)
#define SM_WS_BYTES  (512 * 68 * 4)
#define SM_TOTAL     (SM_WS_BYTES + 16 * 520 * 8)

__global__ __launch_bounds__(512, 1)
void lstm_persistent_kernel(const float* __restrict__ WhE,
                            const float* __restrict__ WhD)
{
    extern __shared__ char smraw[];
    float  (*Ws)[68]   = reinterpret_cast<float(*)[68]>(smraw);
    float2 (*hs2)[520] = reinterpret_cast<float2(*)[520]>(smraw + SM_WS_BYTES);
    u64    (*red)[4]   = reinterpret_cast<u64(*)[4]>(smraw + SM_WS_BYTES);

    const int tid  = threadIdx.x;
    const int half = tid >> 8;          // 0 or 1 (k in [0,256) / [256,512))
    const int ltid = tid & 255;
    const int b0 = blockIdx.x * 32;
    const int j0 = blockIdx.y * 16;

    const int jj = ltid & 15;
    const int bq = ltid >> 4;           // 0..15 (b pair: b0+bq, b0+bq+16)

    // h-staging roles: warp w loads rows (b0+w, b0+w+16) over full k
    const int bqw  = tid >> 5;          // 0..15
    const int lane = tid & 31;

    // ---- init: zero this block's slice of h[0] and c (512 elems, 1 iter) ----
    {
        int bb = tid >> 4, jl = tid & 15;   // 32 x 16
        g_h[0][(b0 + bb) * HID + j0 + jl] = 0.0f;
        g_c[(b0 + bb) * HID + j0 + jl] = 0.0f;
    }

    // ---- load encoder weight slice into smem ----
    // Ws[k][jj*4+g] = Wh[k*G4 + g*HID + j0 + jj]
    for (int idx = tid; idx < 512 * 64; idx += 512) {
        int jjl = idx & 15;
        int k   = (idx >> 4) & 511;
        int g   = idx >> 13;            // 0..3
        Ws[k][jjl * 4 + g] = WhE[(long)k * G4 + g * HID + j0 + jjl];
    }
    // (visibility covered by the __syncthreads inside the first grid_sync)

    for (int s = 0; s < TENC + TDEC; s++) {
        const int phase = (s >= TENC);
        const int t = phase ? s - TENC : s;
        const float* pre = phase ? g_pre_dec : g_pre_enc;
        const int Tdim = phase ? TDEC : TENC;
        const float* hin = g_h[s & 1];
        float* hout = g_h[(s + 1) & 1];
        float* dechs = phase ? (g_dechs + (long)t * BDIM * HID) : (float*)0;

        grid_sync();   // previous step's h (or init) visible everywhere

        if (s == TENC) {   // phase switch: reload weights from decoder matrix
            for (int idx = tid; idx < 512 * 64; idx += 512) {
                int jjl = idx & 15;
                int k   = (idx >> 4) & 511;
                int g   = idx >> 13;
                Ws[k][jjl * 4 + g] = WhD[(long)k * G4 + g * HID + j0 + jjl];
            }
        }

        // ---- stage h tile: hs2[bq][k] = (h[b0+bq][k], h[b0+bq+16][k]) ----
        {
            const float* r0 = hin + (long)(b0 + bqw) * HID;
            const float* r1 = hin + (long)(b0 + bqw + 16) * HID;
            #pragma unroll
            for (int it = 0; it < 4; it++) {
                int k4 = lane * 4 + it * 128;
                float4 lo = *reinterpret_cast<const float4*>(r0 + k4);
                float4 hi = *reinterpret_cast<const float4*>(r1 + k4);
                hs2[bqw][k4 + 0] = make_float2(lo.x, hi.x);
                hs2[bqw][k4 + 1] = make_float2(lo.y, hi.y);
                hs2[bqw][k4 + 2] = make_float2(lo.z, hi.z);
                hs2[bqw][k4 + 3] = make_float2(lo.w, hi.w);
            }
        }
        __syncthreads();

        // ---- prefetch pre-activation gates (latency hidden under k-loop) ----
        float prv[2][4];
        if (half == 0) {
            #pragma unroll
            for (int bl = 0; bl < 2; bl++) {
                const float* pr = pre +
                    ((long)(b0 + bq + bl * 16) * Tdim + t) * G4 + j0 + jj;
                prv[bl][0] = pr[0];
                prv[bl][1] = pr[512];
                prv[bl][2] = pr[1024];
                prv[bl][3] = pr[1536];
            }
        }

        // ---- main FMA loop (all operands in smem) ----
        u64 acc2[4] = {0ull, 0ull, 0ull, 0ull};
        const int kbase = half << 8;
        #pragma unroll 8
        for (int k = kbase; k < kbase + 256; k++) {
            u64 h2 = *reinterpret_cast<const u64*>(&hs2[bq][k]);
            float4 wv = *reinterpret_cast<const float4*>(&Ws[k][jj * 4]);
            acc2[0] = ffma2(h2, dup2(wv.x), acc2[0]);
            acc2[1] = ffma2(h2, dup2(wv.y), acc2[1]);
            acc2[2] = ffma2(h2, dup2(wv.z), acc2[2]);
            acc2[3] = ffma2(h2, dup2(wv.w), acc2[3]);
        }
        __syncthreads();   // compute done before red aliases hs2

        if (half == 1) {
            #pragma unroll
            for (int g = 0; g < 4; g++) red[ltid][g] = acc2[g];
        }
        __syncthreads();

        if (half == 0) {
            float2 av[4];
            #pragma unroll
            for (int g = 0; g < 4; g++) {
                u64 v = fadd2(acc2[g], red[ltid][g]);
                av[g] = *reinterpret_cast<float2*>(&v);
            }
            #pragma unroll
            for (int bl = 0; bl < 2; bl++) {
                int b = b0 + bq + bl * 16;
                int j = j0 + jj;
                float gi = (bl ? av[0].y : av[0].x) + prv[bl][0];
                float gj = (bl ? av[1].y : av[1].x) + prv[bl][1];
                float gf = (bl ? av[2].y : av[2].x) + prv[bl][2];
                float go = (bl ? av[3].y : av[3].x) + prv[bl][3];
                int idx = b * HID + j;
                float cn = g_c[idx] * sigm(gf + 1.0f) + sigm(gi) * tanhf(gj);
                g_c[idx] = cn;
                float hn = tanhf(cn) * sigm(go);
                hout[idx] = hn;
                if (dechs) dechs[idx] = hn;
            }
        }
    }
}

// ---------------- launch ------------------------------------------------------
extern "C" void kernel_launch(void* const* d_in, const int* in_sizes, int n_in,
                              void* d_out, int out_size) {
    (void)out_size;
    const float* frames  = 0;   // 16777216
    const int*   cap_ids = 0;   // 4096
    const float* emb     = 0;   // 9600000
    const float* W_enc   = 0;   // 5242880
    const float* b_enc   = 0;   // 2048 (first seen)
    const float* W_dec   = 0;   // 1662976
    const float* b_dec   = 0;   // 2048 (second seen)
    const float* W_out   = 0;   // 153600
    const float* b_out   = 0;   // 300

    for (int i = 0; i < n_in; i++) {
        long sz = in_sizes[i];
        const void* p = d_in[i];
        if      (sz == 16777216) frames  = (const float*)p;
        else if (sz == 4096)     cap_ids = (const int*)p;
        else if (sz == 9600000)  emb     = (const float*)p;
        else if (sz == 5242880)  W_enc   = (const float*)p;
        else if (sz == 1662976)  W_dec   = (const float*)p;
        else if (sz == 153600)   W_out   = (const float*)p;
        else if (sz == 300)      b_out   = (const float*)p;
        else if (sz == 2048) {
            if (!b_enc) b_enc = (const float*)p;
            else        b_dec = (const float*)p;
        }
    }
    if (!frames || !cap_ids || !emb || !W_enc || !b_enc || !W_dec || !b_dec ||
        !W_out || !b_out) {
        frames  = (const float*)d_in[0];
        cap_ids = (const int*)  d_in[1];
        emb     = (const float*)d_in[2];
        W_enc   = (const float*)d_in[3];
        b_enc   = (const float*)d_in[4];
        W_dec   = (const float*)d_in[5];
        b_dec   = (const float*)d_in[6];
        W_out   = (const float*)d_in[7];
        b_out   = (const float*)d_in[8];
    }
    float* out = (float*)d_out;

    // opt-in to large dynamic smem (idempotent host call, not a stream op)
    cudaFuncSetAttribute(lstm_persistent_kernel,
                         cudaFuncAttributeMaxDynamicSharedMemorySize, SM_TOTAL);

    {   // encoder x-projection: [8192 x 2048] @ [2048 x 2048] + b_enc
        dim3 grid(G4 / 128, (BDIM * TENC) / 128);
        gemm_kernel<0><<<grid, 256>>>(frames, W_enc, b_enc, 0, 0,
                                      BDIM * TENC, G4, DIN);
    }
    {   // decoder x-projection with gather: [4096 x 300] @ [300 x 2048] + b_dec
        dim3 grid(G4 / 128, (BDIM * TDEC) / 128);
        gemm_kernel<1><<<grid, 256>>>(emb, W_dec, b_dec, 0, cap_ids,
                                      BDIM * TDEC, G4, DW);
    }

    // persistent recurrence: all 96 steps in one launch
    {
        const float* WhE = W_enc + (long)DIN * G4;   // h-part rows of W_enc
        const float* WhD = W_dec + (long)DW * G4;    // h-part rows of W_dec
        lstm_persistent_kernel<<<dim3(4, 32), 512, SM_TOTAL>>>(WhE, WhD);
    }

    {   // output projection: [4096 x 512] @ [512 x 300] + b_out
        dim3 grid((DW + 127) / 128, (BDIM * TDEC) / 128);
        gemm_kernel<2><<<grid, 256>>>(0, W_out, b_out, out, 0,
                                      BDIM * TDEC, DW, HID);
    }
}